// round 1
// baseline (speedup 1.0000x reference)
#include <cuda_runtime.h>
#include <math.h>

#define HW 4096
#define WW 64
#define HH 64

// ---------------- device scratch (static globals; no allocation) ----------------
__device__ float g_emb [12*HW*96];
__device__ float g_qkv [12*HW*288];
__device__ float g_off1[4*HW*96];
__device__ float g_off2[4*HW*96];
__device__ float g_om  [4*HW*216];
__device__ float g_wall[6*4*HW];
__device__ float g_vall[6*4*HW*96];
__device__ float g_f   [12*HW*96];
__device__ float g_cfwt [64*9*96];
__device__ float g_qkvwt[96*288];
__device__ float g_qkvb [288];
__device__ float g_oc1wt[192*9*96];
__device__ float g_oc2wt[96*9*96];
__device__ float g_omwt [96*9*216];
__device__ float g_clwt [96*9*64];

// ---------------- weight transpose prep: w[d][k] -> wt[k][d] ----------------
__global__ void prep_wt(const float* __restrict__ w, float* __restrict__ wt,
                        int cout, int kk) {
    int i = blockIdx.x*256 + threadIdx.x;
    if (i < cout*kk) {
        int d = i / kk, k = i - d*kk;
        wt[k*cout + d] = w[i];
    }
}

__global__ void prep_qkv(const float* __restrict__ wq, const float* __restrict__ wk,
                         const float* __restrict__ wv,
                         const float* __restrict__ bq, const float* __restrict__ bk,
                         const float* __restrict__ bv,
                         float* __restrict__ wt, float* __restrict__ bb) {
    int i = blockIdx.x*256 + threadIdx.x;
    if (i < 96*96) {
        int d = i / 96, c = i - d*96;
        wt[c*288 + d]       = wq[i];
        wt[c*288 + 96 + d]  = wk[i];
        wt[c*288 + 192 + d] = wv[i];
    }
    if (i < 96) { bb[i] = bq[i]; bb[96+i] = bk[i]; bb[192+i] = bv[i]; }
}

// ---------------- generic conv (3x3 pad1 or 1x1), implicit GEMM tiling ----------------
// block: 64-pixel row x TILE_D out-channels; thread: 4 outch x 4 px registers.
// input channel-last (or NCHW for the first conv); weights pre-transposed [cin*KSQ][COUT].
template<int CIN, int COUT, int TILE_D, int KS, bool IN_NCHW, bool LRELU, bool NCHW_OUT>
__global__ void __launch_bounds__(16*(TILE_D/4))
conv_k(const float* __restrict__ inA, int aStride,
       const float* __restrict__ inB, int bStride, int cSplit, int inPixStride,
       const float* __restrict__ wt, const float* __restrict__ bias,
       float* __restrict__ out, int outImgStride, int outPixStride, int outOff,
       const float* __restrict__ resid)
{
    constexpr int NT   = 16*(TILE_D/4);
    constexpr int KSQ  = KS*KS;
    constexpr int ROWS = (KS==3) ? 3 : 1;
    constexpr int IPAD = (KS==3) ? 68 : 64;
    constexpr int ICOL = (KS==3) ? 66 : 64;
    constexpr int CCH  = 8;
    __shared__ __align__(16) float s_in[CCH][ROWS][IPAD];
    __shared__ __align__(16) float s_w [CCH][KSQ][TILE_D];

    const int tx  = threadIdx.x, ty = threadIdx.y;
    const int tid = ty*16 + tx;
    const int y   = blockIdx.y;
    const int z   = blockIdx.z;
    const int d0  = blockIdx.x*TILE_D + 4*ty;
    const int px0 = 4*tx;

    float acc[4][4];
#pragma unroll
    for (int dj=0; dj<4; dj++) {
        float bv = bias[d0+dj];
#pragma unroll
        for (int pj=0; pj<4; pj++) acc[dj][pj] = bv;
    }

    for (int c0 = 0; c0 < CIN; c0 += CCH) {
        __syncthreads();
        // --- input tile ---
        for (int i = tid; i < CCH*ROWS*ICOL; i += NT) {
            int cc, col, r;
            if (IN_NCHW) { col = i % ICOL; cc = (i/ICOL)%CCH; r = i/(ICOL*CCH); }
            else         { cc = i % CCH; col = (i/CCH)%ICOL; r = i/(CCH*ICOL); }
            float v = 0.f;
            if (KS == 3) {
                int xx = col-1, yy = y-1+r;
                if (xx >= 0 && xx < WW && yy >= 0 && yy < HH) {
                    int c = c0+cc;
                    if (IN_NCHW) v = inA[z*aStride + c*HW + yy*WW + xx];
                    else {
                        const float* base = (c < cSplit) ? (inA + z*aStride + c)
                                                         : (inB + z*bStride + (c - cSplit));
                        v = base[(yy*WW+xx)*inPixStride];
                    }
                }
            } else {
                int c = c0+cc;
                const float* base = (c < cSplit) ? (inA + z*aStride + c)
                                                 : (inB + z*bStride + (c - cSplit));
                v = base[(y*WW+col)*inPixStride];
            }
            s_in[cc][r][col] = v;
        }
        // --- weights ---
        for (int i = tid; i < CCH*KSQ*TILE_D; i += NT) {
            int d = i % TILE_D; int tap = (i/TILE_D)%KSQ; int cc = i/(TILE_D*KSQ);
            s_w[cc][tap][d] = wt[((c0+cc)*KSQ + tap)*COUT + blockIdx.x*TILE_D + d];
        }
        __syncthreads();
#pragma unroll
        for (int cc=0; cc<CCH; cc++) {
            if (KS == 3) {
                float r[3][6];
#pragma unroll
                for (int rr=0; rr<3; rr++) {
                    float4 a = *(const float4*)&s_in[cc][rr][px0];
                    r[rr][0]=a.x; r[rr][1]=a.y; r[rr][2]=a.z; r[rr][3]=a.w;
                    r[rr][4]=s_in[cc][rr][px0+4];
                    r[rr][5]=s_in[cc][rr][px0+5];
                }
#pragma unroll
                for (int tap=0; tap<9; tap++) {
                    float4 w = *(const float4*)&s_w[cc][tap][4*ty];
                    const int dy = tap/3, dx = tap%3;
#pragma unroll
                    for (int pj=0; pj<4; pj++) {
                        float v = r[dy][dx+pj];
                        acc[0][pj] = fmaf(w.x, v, acc[0][pj]);
                        acc[1][pj] = fmaf(w.y, v, acc[1][pj]);
                        acc[2][pj] = fmaf(w.z, v, acc[2][pj]);
                        acc[3][pj] = fmaf(w.w, v, acc[3][pj]);
                    }
                }
            } else {
                float4 a = *(const float4*)&s_in[cc][0][px0];
                float rv[4] = {a.x, a.y, a.z, a.w};
                float4 w = *(const float4*)&s_w[cc][0][4*ty];
#pragma unroll
                for (int pj=0; pj<4; pj++) {
                    float v = rv[pj];
                    acc[0][pj] = fmaf(w.x, v, acc[0][pj]);
                    acc[1][pj] = fmaf(w.y, v, acc[1][pj]);
                    acc[2][pj] = fmaf(w.z, v, acc[2][pj]);
                    acc[3][pj] = fmaf(w.w, v, acc[3][pj]);
                }
            }
        }
    }

    if (LRELU) {
#pragma unroll
        for (int dj=0; dj<4; dj++)
#pragma unroll
            for (int pj=0; pj<4; pj++) {
                float v = acc[dj][pj];
                acc[dj][pj] = (v >= 0.f) ? v : 0.1f*v;
            }
    }

    if (!NCHW_OUT) {
#pragma unroll
        for (int pj=0; pj<4; pj++) {
            float4 o = make_float4(acc[0][pj], acc[1][pj], acc[2][pj], acc[3][pj]);
            *(float4*)&out[z*outImgStride + (y*WW + px0 + pj)*outPixStride + outOff + d0] = o;
        }
    } else {
#pragma unroll
        for (int dj=0; dj<4; dj++) {
            int idx = (z*COUT + d0+dj)*HW + y*WW + px0;
            float4 rr = *(const float4*)&resid[idx];
            float4 o = make_float4(acc[dj][0]+rr.x, acc[dj][1]+rr.y,
                                   acc[dj][2]+rr.z, acc[dj][3]+rr.w);
            *(float4*)&out[idx] = o;
        }
    }
}

// ---------------- deformable top-2 attention: 1 warp per pixel ----------------
// w_ori = sum_t corr[t] * rel[idx[t]]  (exact algebraic identity, no k re-sampling)
__global__ void __launch_bounds__(128) attn_k(
    const float* __restrict__ qkv, int jj, int ii,
    const float* __restrict__ om,
    float* __restrict__ w_out, float* __restrict__ v_out)
{
    __shared__ __align__(16) float4 s_wgt[4][72];
    __shared__ __align__(16) int4   s_off[4][72];
    const int warp = threadIdx.x >> 5;
    const int lane = threadIdx.x & 31;
    const int p = blockIdx.x*4 + warp;
    const int b = blockIdx.y;
    const int y = p >> 6, x = p & 63;
    const float* ombase = om + (b*HW + p)*216;

    // phase A: bilinear params per (group, point) — weights include mask & validity
    for (int t = lane; t < 72; t += 32) {
        float oy = ombase[t];
        float ox = ombase[72 + t];
        float mm = ombase[144 + t];
        int n = t % 9;
        float m  = 1.f/(1.f + expf(-mm));
        float py = oy + (float)(n/3 - 1 + y);
        float px = ox + (float)(n%3 - 1 + x);
        float y0f = floorf(py), x0f = floorf(px);
        float wy = py - y0f, wx = px - x0f;
        int iy0 = (int)y0f, ix0 = (int)x0f;
        int iy1 = iy0 + 1, ix1 = ix0 + 1;
        float vy0 = (iy0 >= 0 && iy0 < HH) ? 1.f : 0.f;
        float vy1 = (iy1 >= 0 && iy1 < HH) ? 1.f : 0.f;
        float vx0 = (ix0 >= 0 && ix0 < WW) ? 1.f : 0.f;
        float vx1 = (ix1 >= 0 && ix1 < WW) ? 1.f : 0.f;
        int cy0 = min(max(iy0,0),HH-1), cy1 = min(max(iy1,0),HH-1);
        int cx0 = min(max(ix0,0),WW-1), cx1 = min(max(ix1,0),WW-1);
        float wy0 = 1.f - wy, wx0 = 1.f - wx;
        s_wgt[warp][t] = make_float4(m*wy0*wx0*vy0*vx0, m*wy0*wx *vy0*vx1,
                                     m*wy *wx0*vy1*vx0, m*wy *wx *vy1*vx1);
        s_off[warp][t] = make_int4((cy0*WW+cx0)*288, (cy0*WW+cx1)*288,
                                   (cy1*WW+cx0)*288, (cy1*WW+cx1)*288);
    }
    __syncwarp();

    const float* qp = qkv + ((b*3+jj)*HW + p)*288;
    const float* kb = qkv + (b*3+ii)*HW*288 + 96;     // k plane (channel-last, stride 288)
    const float qv0 = qp[lane], qv1 = qp[lane+32], qv2 = qp[lane+64];
    const int g0 = lane/12, g1 = (lane+32)/12, g2 = (lane+64)/12;

    float rel[9];
#pragma unroll
    for (int n=0; n<9; n++) {
        float partial;
        {
            float4 W = s_wgt[warp][g0*9+n]; int4 O = s_off[warp][g0*9+n];
            const float* kk = kb + lane;
            float s = W.x*__ldg(kk+O.x) + W.y*__ldg(kk+O.y)
                    + W.z*__ldg(kk+O.z) + W.w*__ldg(kk+O.w);
            partial = s*qv0;
        }
        {
            float4 W = s_wgt[warp][g1*9+n]; int4 O = s_off[warp][g1*9+n];
            const float* kk = kb + lane + 32;
            float s = W.x*__ldg(kk+O.x) + W.y*__ldg(kk+O.y)
                    + W.z*__ldg(kk+O.z) + W.w*__ldg(kk+O.w);
            partial = fmaf(s, qv1, partial);
        }
        {
            float4 W = s_wgt[warp][g2*9+n]; int4 O = s_off[warp][g2*9+n];
            const float* kk = kb + lane + 64;
            float s = W.x*__ldg(kk+O.x) + W.y*__ldg(kk+O.y)
                    + W.z*__ldg(kk+O.z) + W.w*__ldg(kk+O.w);
            partial = fmaf(s, qv2, partial);
        }
#pragma unroll
        for (int o=16; o>0; o>>=1) partial += __shfl_xor_sync(0xffffffffu, partial, o);
        rel[n] = partial;
    }

    // top-2 (ties: lower index first, matching jax.lax.top_k)
    float b1 = rel[0]; int i1 = 0; float b2 = -1e30f; int i2 = 0;
#pragma unroll
    for (int n=1; n<9; n++) {
        if (rel[n] > b1)      { b2 = b1; i2 = i1; b1 = rel[n]; i1 = n; }
        else if (rel[n] > b2) { b2 = rel[n]; i2 = n; }
    }
    float c1 = 1.f/(1.f + expf(b2 - b1));
    float c2 = 1.f - c1;
    if (lane == 0) w_out[b*HW + p] = c1*b1 + c2*b2;

    // v_re: sample v only at the two selected points
    const float* vb = kb + 96;
    float* vo = v_out + (b*HW + p)*96;
    const int cs[3] = {lane, lane+32, lane+64};
    const int gs[3] = {g0, g1, g2};
#pragma unroll
    for (int j=0; j<3; j++) {
        int c = cs[j], g = gs[j];
        float4 W1 = s_wgt[warp][g*9+i1]; int4 O1 = s_off[warp][g*9+i1];
        float4 W2 = s_wgt[warp][g*9+i2]; int4 O2 = s_off[warp][g*9+i2];
        const float* vv = vb + c;
        float s1 = W1.x*__ldg(vv+O1.x)+W1.y*__ldg(vv+O1.y)+W1.z*__ldg(vv+O1.z)+W1.w*__ldg(vv+O1.w);
        float s2 = W2.x*__ldg(vv+O2.x)+W2.y*__ldg(vv+O2.y)+W2.z*__ldg(vv+O2.z)+W2.w*__ldg(vv+O2.w);
        vo[c] = c1*s1 + c2*s2;
    }
}

// ---------------- fuse: softmax over the 2 pairs per target frame ----------------
__global__ void fuse_k(const float* __restrict__ w_all, const float* __restrict__ v_all,
                       float* __restrict__ f)
{
    int i = blockIdx.x*256 + threadIdx.x;    // over 12*HW*96
    if (i >= 12*HW*96) return;
    int c = i % 96; int rest = i / 96; int p = rest % HW; int img = rest / HW;
    int jj = img % 3, b = img / 3;
    int p0 = jj*2, p1 = jj*2+1;
    float w0 = w_all[(p0*4 + b)*HW + p];
    float w1 = w_all[(p1*4 + b)*HW + p];
    float mx = fmaxf(w0, w1);
    float e0 = expf(w0-mx), e1 = expf(w1-mx);
    float inv = 1.f/(e0+e1);
    float v0 = v_all[((p0*4+b)*HW + p)*96 + c];
    float v1 = v_all[((p1*4+b)*HW + p)*96 + c];
    f[i] = (e0*v0 + e1*v1)*inv;
}

// ---------------- host ----------------
static float* symaddr(const void* s) {
    void* p = nullptr;
    cudaGetSymbolAddress(&p, s);
    return (float*)p;
}

extern "C" void kernel_launch(void* const* d_in, const int* in_sizes, int n_in,
                              void* d_out, int out_size)
{
    const float* fea   = (const float*)d_in[0];
    const float* cf_w  = (const float*)d_in[1];
    const float* cf_b  = (const float*)d_in[2];
    const float* wq    = (const float*)d_in[3];
    const float* bq    = (const float*)d_in[4];
    const float* wk    = (const float*)d_in[5];
    const float* bk    = (const float*)d_in[6];
    const float* wv    = (const float*)d_in[7];
    const float* bv    = (const float*)d_in[8];
    const float* oc1_w = (const float*)d_in[9];
    const float* oc1_b = (const float*)d_in[10];
    const float* oc2_w = (const float*)d_in[11];
    const float* oc2_b = (const float*)d_in[12];
    const float* om_w  = (const float*)d_in[13];
    const float* om_b  = (const float*)d_in[14];
    const float* cl_w  = (const float*)d_in[15];
    const float* cl_b  = (const float*)d_in[16];
    float* out = (float*)d_out;

    float* emb   = symaddr(g_emb);
    float* qkv   = symaddr(g_qkv);
    float* off1  = symaddr(g_off1);
    float* off2  = symaddr(g_off2);
    float* omb   = symaddr(g_om);
    float* wall  = symaddr(g_wall);
    float* vall  = symaddr(g_vall);
    float* fbuf  = symaddr(g_f);
    float* cfwt  = symaddr(g_cfwt);
    float* qkvwt = symaddr(g_qkvwt);
    float* qkvb  = symaddr(g_qkvb);
    float* oc1wt = symaddr(g_oc1wt);
    float* oc2wt = symaddr(g_oc2wt);
    float* omwt  = symaddr(g_omwt);
    float* clwt  = symaddr(g_clwt);

    // weight prep (tiny)
    prep_wt <<<(96*576 +255)/256, 256>>>(cf_w,  cfwt,  96, 576);
    prep_qkv<<<(96*96  +255)/256, 256>>>(wq, wk, wv, bq, bk, bv, qkvwt, qkvb);
    prep_wt <<<(96*1728+255)/256, 256>>>(oc1_w, oc1wt, 96, 1728);
    prep_wt <<<(96*864 +255)/256, 256>>>(oc2_w, oc2wt, 96, 864);
    prep_wt <<<(216*864+255)/256, 256>>>(om_w,  omwt, 216, 864);
    prep_wt <<<(64*864 +255)/256, 256>>>(cl_w,  clwt,  64, 864);

    // emb = conv3x3(fea) — NCHW input, channel-last output
    conv_k<64,96,48,3,true,false,false><<<dim3(2,64,12), dim3(16,12)>>>(
        fea, 64*HW, fea, 0, 64, 1, cfwt, cf_b, emb, HW*96, 96, 0, nullptr);

    // qkv = 1x1(emb) — fused q|k|v into stride-288 layout
    conv_k<96,288,48,1,false,false,false><<<dim3(6,64,12), dim3(16,12)>>>(
        emb, HW*96, emb, 0, 96, 96, qkvwt, qkvb, qkv, HW*288, 288, 0, nullptr);

    int pidx = 0;
    for (int jj = 0; jj < 3; jj++) {
        for (int ii = 0; ii < 3; ii++) {
            if (ii == jj) continue;
            const float* qA = qkv + jj*HW*288;          // q of frame jj (ch 0..95)
            const float* kB = qkv + ii*HW*288 + 96;     // k of frame ii (ch 96..191)
            // oc1: conv3x3(concat(q,k)) + lrelu (virtual concat via split pointers)
            conv_k<192,96,48,3,false,true,false><<<dim3(2,64,4), dim3(16,12)>>>(
                qA, 3*HW*288, kB, 3*HW*288, 96, 288, oc1wt, oc1_b, off1, HW*96, 96, 0, nullptr);
            // oc2 + lrelu
            conv_k<96,96,48,3,false,true,false><<<dim3(2,64,4), dim3(16,12)>>>(
                off1, HW*96, off1, 0, 96, 96, oc2wt, oc2_b, off2, HW*96, 96, 0, nullptr);
            // om (216 ch: off_y | off_x | mask-logits)
            conv_k<96,216,72,3,false,false,false><<<dim3(3,64,4), dim3(16,18)>>>(
                off2, HW*96, off2, 0, 96, 96, omwt, om_b, omb, HW*216, 216, 0, nullptr);
            // deformable top-2 attention
            attn_k<<<dim3(1024,4), 128>>>(qkv, jj, ii, omb,
                wall + pidx*4*HW, vall + pidx*4*HW*96);
            pidx++;
        }
    }

    // temporal softmax fusion -> f (channel-last)
    fuse_k<<<(12*HW*96+255)/256, 256>>>(wall, vall, fbuf);

    // cl conv -> NCHW output + residual
    conv_k<96,64,64,3,false,false,true><<<dim3(1,64,12), dim3(16,16)>>>(
        fbuf, HW*96, fbuf, 0, 96, 96, clwt, cl_b, out, 0, 0, 0, fea);

    (void)in_sizes; (void)n_in; (void)out_size;
}

// round 2
// speedup vs baseline: 1.3000x; 1.3000x over previous
#include <cuda_runtime.h>
#include <math.h>

#define HW 4096
#define WW 64
#define HH 64

typedef unsigned long long u64;

// ---------------- packed f32x2 helpers (FFMA2 — 2x fp32 FMA throughput) ----------------
__device__ __forceinline__ u64 pk(float v) {
    u64 r; asm("mov.b64 %0, {%1, %1};" : "=l"(r) : "f"(v)); return r;
}
__device__ __forceinline__ u64 pk2(float a, float b) {
    u64 r; asm("mov.b64 %0, {%1, %2};" : "=l"(r) : "f"(a), "f"(b)); return r;
}
__device__ __forceinline__ void fma2(u64& d, u64 a, u64 b) {
    asm("fma.rn.f32x2 %0, %1, %2, %0;" : "+l"(d) : "l"(a), "l"(b));
}
__device__ __forceinline__ float2 up2(u64 v) {
    float2 f; asm("mov.b64 {%0, %1}, %2;" : "=f"(f.x), "=f"(f.y) : "l"(v)); return f;
}

// ---------------- device scratch (static globals; no allocation) ----------------
__device__ float g_emb [12*HW*96];
__device__ float g_qkv [12*HW*288];
__device__ float g_off1[6*4*HW*96];
__device__ float g_off2[6*4*HW*96];
__device__ float g_om  [6*4*HW*216];
__device__ float g_wall[6*4*HW];
__device__ float g_vall[6*4*HW*96];
__device__ float g_f   [12*HW*96];
__device__ float g_cfwt [64*9*96];
__device__ float g_qkvwt[96*288];
__device__ float g_qkvb [288];
__device__ float g_oc1wt[192*9*96];
__device__ float g_oc2wt[96*9*96];
__device__ float g_omwt [96*9*216];
__device__ float g_clwt [96*9*64];

// ---------------- weight transpose prep: w[d][k] -> wt[k][d] ----------------
__global__ void prep_wt(const float* __restrict__ w, float* __restrict__ wt,
                        int cout, int kk) {
    int i = blockIdx.x*256 + threadIdx.x;
    if (i < cout*kk) {
        int d = i / kk, k = i - d*kk;
        wt[k*cout + d] = w[i];
    }
}

__global__ void prep_qkv(const float* __restrict__ wq, const float* __restrict__ wk,
                         const float* __restrict__ wv,
                         const float* __restrict__ bq, const float* __restrict__ bk,
                         const float* __restrict__ bv,
                         float* __restrict__ wt, float* __restrict__ bb) {
    int i = blockIdx.x*256 + threadIdx.x;
    if (i < 96*96) {
        int d = i / 96, c = i - d*96;
        wt[c*288 + d]       = wq[i];
        wt[c*288 + 96 + d]  = wk[i];
        wt[c*288 + 192 + d] = wv[i];
    }
    if (i < 96) { bb[i] = bq[i]; bb[96+i] = bk[i]; bb[192+i] = bv[i]; }
}

// ---------------- generic conv (3x3 pad1 or 1x1), implicit GEMM tiling ----------------
// block: 64-pixel row x TILE_D out-channels; thread: 4 outch x 4 px registers.
// PAIRQK mode: z in [0,24) = pair*4 + batch; input = virtual concat(q[jj], k[ii]) from qkv.
template<int CIN, int COUT, int TILE_D, int KS, bool IN_NCHW, bool LRELU, bool NCHW_OUT, bool PAIRQK>
__global__ void __launch_bounds__(16*(TILE_D/4))
conv_k(const float* __restrict__ inA, int aStride,
       const float* __restrict__ inB, int bStride, int cSplit, int inPixStride,
       const float* __restrict__ wt, const float* __restrict__ bias,
       float* __restrict__ out, int outImgStride, int outPixStride, int outOff,
       const float* __restrict__ resid)
{
    constexpr int NT   = 16*(TILE_D/4);
    constexpr int KSQ  = KS*KS;
    constexpr int ROWS = (KS==3) ? 3 : 1;
    constexpr int IPAD = (KS==3) ? 68 : 64;
    constexpr int ICOL = (KS==3) ? 66 : 64;
    constexpr int CCH  = 8;
    __shared__ __align__(16) float s_in[CCH][ROWS][IPAD];
    __shared__ __align__(16) float s_w [CCH][KSQ][TILE_D];

    const int tx  = threadIdx.x, ty = threadIdx.y;
    const int tid = ty*16 + tx;
    const int y   = blockIdx.y;
    const int z   = blockIdx.z;
    const int d0  = blockIdx.x*TILE_D + 4*ty;
    const int px0 = 4*tx;

    // resolve input pointers
    const float* baseA = inA;
    const float* baseB = inB;
    int strideA = aStride, strideB = bStride, zz = z;
    if (PAIRQK) {
        int pair = z >> 2, bb = z & 3;
        int jj = pair >> 1;
        int l  = pair & 1;
        int ii = l ? ((jj==2) ? 1 : 2) : ((jj==0) ? 1 : 0);
        baseA = inA + (bb*3 + jj)*HW*288;          // q channels 0..95
        baseB = inA + (bb*3 + ii)*HW*288 + 96;     // k channels 0..95
        strideA = 0; strideB = 0; zz = 0;
    }

    u64 acc2[2][4];
#pragma unroll
    for (int h=0; h<2; h++) {
        u64 bv = pk2(bias[d0+2*h], bias[d0+2*h+1]);
#pragma unroll
        for (int pj=0; pj<4; pj++) acc2[h][pj] = bv;
    }

    for (int c0 = 0; c0 < CIN; c0 += CCH) {
        __syncthreads();
        // --- input tile ---
        for (int i = tid; i < CCH*ROWS*ICOL; i += NT) {
            int cc, col, r;
            if (IN_NCHW) { col = i % ICOL; cc = (i/ICOL)%CCH; r = i/(ICOL*CCH); }
            else         { cc = i % CCH; col = (i/CCH)%ICOL; r = i/(CCH*ICOL); }
            float v = 0.f;
            if (KS == 3) {
                int xx = col-1, yy = y-1+r;
                if (xx >= 0 && xx < WW && yy >= 0 && yy < HH) {
                    int c = c0+cc;
                    if (IN_NCHW) v = baseA[zz*strideA + c*HW + yy*WW + xx];
                    else {
                        const float* base = (c < cSplit) ? (baseA + zz*strideA + c)
                                                         : (baseB + zz*strideB + (c - cSplit));
                        v = base[(yy*WW+xx)*inPixStride];
                    }
                }
            } else {
                int c = c0+cc;
                const float* base = (c < cSplit) ? (baseA + zz*strideA + c)
                                                 : (baseB + zz*strideB + (c - cSplit));
                v = base[(y*WW+col)*inPixStride];
            }
            s_in[cc][r][col] = v;
        }
        // --- weights ---
        for (int i = tid; i < CCH*KSQ*TILE_D; i += NT) {
            int d = i % TILE_D; int tap = (i/TILE_D)%KSQ; int cc = i/(TILE_D*KSQ);
            s_w[cc][tap][d] = wt[((c0+cc)*KSQ + tap)*COUT + blockIdx.x*TILE_D + d];
        }
        __syncthreads();
#pragma unroll
        for (int cc=0; cc<CCH; cc++) {
            if (KS == 3) {
                float r[3][6];
#pragma unroll
                for (int rr=0; rr<3; rr++) {
                    float4 a = *(const float4*)&s_in[cc][rr][px0];
                    r[rr][0]=a.x; r[rr][1]=a.y; r[rr][2]=a.z; r[rr][3]=a.w;
                    r[rr][4]=s_in[cc][rr][px0+4];
                    r[rr][5]=s_in[cc][rr][px0+5];
                }
#pragma unroll
                for (int tap=0; tap<9; tap++) {
                    const u64* wp = (const u64*)&s_w[cc][tap][4*ty];
                    u64 w01 = wp[0], w23 = wp[1];
                    const int dy = tap/3, dx = tap%3;
#pragma unroll
                    for (int pj=0; pj<4; pj++) {
                        u64 a = pk(r[dy][dx+pj]);
                        fma2(acc2[0][pj], a, w01);
                        fma2(acc2[1][pj], a, w23);
                    }
                }
            } else {
                float4 a = *(const float4*)&s_in[cc][0][px0];
                float rv[4] = {a.x, a.y, a.z, a.w};
                const u64* wp = (const u64*)&s_w[cc][0][4*ty];
                u64 w01 = wp[0], w23 = wp[1];
#pragma unroll
                for (int pj=0; pj<4; pj++) {
                    u64 a = pk(rv[pj]);
                    fma2(acc2[0][pj], a, w01);
                    fma2(acc2[1][pj], a, w23);
                }
            }
        }
    }

    // unpack
    float acc[4][4];
#pragma unroll
    for (int h=0; h<2; h++)
#pragma unroll
        for (int pj=0; pj<4; pj++) {
            float2 f = up2(acc2[h][pj]);
            acc[2*h][pj] = f.x; acc[2*h+1][pj] = f.y;
        }

    if (LRELU) {
#pragma unroll
        for (int dj=0; dj<4; dj++)
#pragma unroll
            for (int pj=0; pj<4; pj++) {
                float v = acc[dj][pj];
                acc[dj][pj] = (v >= 0.f) ? v : 0.1f*v;
            }
    }

    if (!NCHW_OUT) {
#pragma unroll
        for (int pj=0; pj<4; pj++) {
            float4 o = make_float4(acc[0][pj], acc[1][pj], acc[2][pj], acc[3][pj]);
            *(float4*)&out[z*outImgStride + (y*WW + px0 + pj)*outPixStride + outOff + d0] = o;
        }
    } else {
#pragma unroll
        for (int dj=0; dj<4; dj++) {
            int idx = (z*COUT + d0+dj)*HW + y*WW + px0;
            float4 rr = *(const float4*)&resid[idx];
            float4 o = make_float4(acc[dj][0]+rr.x, acc[dj][1]+rr.y,
                                   acc[dj][2]+rr.z, acc[dj][3]+rr.w);
            *(float4*)&out[idx] = o;
        }
    }
}

// ---------------- deformable top-2 attention: 1 warp per pixel, batched over pairs ----------------
__global__ void __launch_bounds__(128) attn_k(
    const float* __restrict__ qkv,
    const float* __restrict__ om_all,
    float* __restrict__ w_all, float* __restrict__ v_all)
{
    __shared__ __align__(16) float4 s_wgt[4][72];
    __shared__ __align__(16) int4   s_off[4][72];
    const int warp = threadIdx.x >> 5;
    const int lane = threadIdx.x & 31;
    const int p = blockIdx.x*4 + warp;
    const int b = blockIdx.y;
    const int pair = blockIdx.z;
    const int jj = pair >> 1;
    const int l  = pair & 1;
    const int ii = l ? ((jj==2) ? 1 : 2) : ((jj==0) ? 1 : 0);
    const int y = p >> 6, x = p & 63;
    const float* ombase = om_all + ((pair*4 + b)*HW + p)*216;

    for (int t = lane; t < 72; t += 32) {
        float oy = ombase[t];
        float ox = ombase[72 + t];
        float mm = ombase[144 + t];
        int n = t % 9;
        float m  = 1.f/(1.f + expf(-mm));
        float py = oy + (float)(n/3 - 1 + y);
        float px = ox + (float)(n%3 - 1 + x);
        float y0f = floorf(py), x0f = floorf(px);
        float wy = py - y0f, wx = px - x0f;
        int iy0 = (int)y0f, ix0 = (int)x0f;
        int iy1 = iy0 + 1, ix1 = ix0 + 1;
        float vy0 = (iy0 >= 0 && iy0 < HH) ? 1.f : 0.f;
        float vy1 = (iy1 >= 0 && iy1 < HH) ? 1.f : 0.f;
        float vx0 = (ix0 >= 0 && ix0 < WW) ? 1.f : 0.f;
        float vx1 = (ix1 >= 0 && ix1 < WW) ? 1.f : 0.f;
        int cy0 = min(max(iy0,0),HH-1), cy1 = min(max(iy1,0),HH-1);
        int cx0 = min(max(ix0,0),WW-1), cx1 = min(max(ix1,0),WW-1);
        float wy0 = 1.f - wy, wx0 = 1.f - wx;
        s_wgt[warp][t] = make_float4(m*wy0*wx0*vy0*vx0, m*wy0*wx *vy0*vx1,
                                     m*wy *wx0*vy1*vx0, m*wy *wx *vy1*vx1);
        s_off[warp][t] = make_int4((cy0*WW+cx0)*288, (cy0*WW+cx1)*288,
                                   (cy1*WW+cx0)*288, (cy1*WW+cx1)*288);
    }
    __syncwarp();

    const float* qp = qkv + ((b*3+jj)*HW + p)*288;
    const float* kb = qkv + (b*3+ii)*HW*288 + 96;
    const float qv0 = qp[lane], qv1 = qp[lane+32], qv2 = qp[lane+64];
    const int g0 = lane/12, g1 = (lane+32)/12, g2 = (lane+64)/12;

    float rel[9];
#pragma unroll
    for (int n=0; n<9; n++) {
        float partial;
        {
            float4 W = s_wgt[warp][g0*9+n]; int4 O = s_off[warp][g0*9+n];
            const float* kk = kb + lane;
            float s = W.x*__ldg(kk+O.x) + W.y*__ldg(kk+O.y)
                    + W.z*__ldg(kk+O.z) + W.w*__ldg(kk+O.w);
            partial = s*qv0;
        }
        {
            float4 W = s_wgt[warp][g1*9+n]; int4 O = s_off[warp][g1*9+n];
            const float* kk = kb + lane + 32;
            float s = W.x*__ldg(kk+O.x) + W.y*__ldg(kk+O.y)
                    + W.z*__ldg(kk+O.z) + W.w*__ldg(kk+O.w);
            partial = fmaf(s, qv1, partial);
        }
        {
            float4 W = s_wgt[warp][g2*9+n]; int4 O = s_off[warp][g2*9+n];
            const float* kk = kb + lane + 64;
            float s = W.x*__ldg(kk+O.x) + W.y*__ldg(kk+O.y)
                    + W.z*__ldg(kk+O.z) + W.w*__ldg(kk+O.w);
            partial = fmaf(s, qv2, partial);
        }
#pragma unroll
        for (int o=16; o>0; o>>=1) partial += __shfl_xor_sync(0xffffffffu, partial, o);
        rel[n] = partial;
    }

    float b1 = rel[0]; int i1 = 0; float b2 = -1e30f; int i2 = 0;
#pragma unroll
    for (int n=1; n<9; n++) {
        if (rel[n] > b1)      { b2 = b1; i2 = i1; b1 = rel[n]; i1 = n; }
        else if (rel[n] > b2) { b2 = rel[n]; i2 = n; }
    }
    float c1 = 1.f/(1.f + expf(b2 - b1));
    float c2 = 1.f - c1;
    if (lane == 0) w_all[(pair*4 + b)*HW + p] = c1*b1 + c2*b2;

    const float* vb = kb + 96;
    float* vo = v_all + ((pair*4 + b)*HW + p)*96;
    const int cs[3] = {lane, lane+32, lane+64};
    const int gs[3] = {g0, g1, g2};
#pragma unroll
    for (int j=0; j<3; j++) {
        int c = cs[j], g = gs[j];
        float4 W1 = s_wgt[warp][g*9+i1]; int4 O1 = s_off[warp][g*9+i1];
        float4 W2 = s_wgt[warp][g*9+i2]; int4 O2 = s_off[warp][g*9+i2];
        const float* vv = vb + c;
        float s1 = W1.x*__ldg(vv+O1.x)+W1.y*__ldg(vv+O1.y)+W1.z*__ldg(vv+O1.z)+W1.w*__ldg(vv+O1.w);
        float s2 = W2.x*__ldg(vv+O2.x)+W2.y*__ldg(vv+O2.y)+W2.z*__ldg(vv+O2.z)+W2.w*__ldg(vv+O2.w);
        vo[c] = c1*s1 + c2*s2;
    }
}

// ---------------- fuse: softmax over the 2 pairs per target frame ----------------
__global__ void fuse_k(const float* __restrict__ w_all, const float* __restrict__ v_all,
                       float* __restrict__ f)
{
    int i = blockIdx.x*256 + threadIdx.x;
    if (i >= 12*HW*96) return;
    int c = i % 96; int rest = i / 96; int p = rest % HW; int img = rest / HW;
    int jj = img % 3, b = img / 3;
    int p0 = jj*2, p1 = jj*2+1;
    float w0 = w_all[(p0*4 + b)*HW + p];
    float w1 = w_all[(p1*4 + b)*HW + p];
    float mx = fmaxf(w0, w1);
    float e0 = expf(w0-mx), e1 = expf(w1-mx);
    float inv = 1.f/(e0+e1);
    float v0 = v_all[((p0*4+b)*HW + p)*96 + c];
    float v1 = v_all[((p1*4+b)*HW + p)*96 + c];
    f[i] = (e0*v0 + e1*v1)*inv;
}

// ---------------- host ----------------
static float* symaddr(const void* s) {
    void* p = nullptr;
    cudaGetSymbolAddress(&p, s);
    return (float*)p;
}

extern "C" void kernel_launch(void* const* d_in, const int* in_sizes, int n_in,
                              void* d_out, int out_size)
{
    const float* fea   = (const float*)d_in[0];
    const float* cf_w  = (const float*)d_in[1];
    const float* cf_b  = (const float*)d_in[2];
    const float* wq    = (const float*)d_in[3];
    const float* bq    = (const float*)d_in[4];
    const float* wk    = (const float*)d_in[5];
    const float* bk    = (const float*)d_in[6];
    const float* wv    = (const float*)d_in[7];
    const float* bv    = (const float*)d_in[8];
    const float* oc1_w = (const float*)d_in[9];
    const float* oc1_b = (const float*)d_in[10];
    const float* oc2_w = (const float*)d_in[11];
    const float* oc2_b = (const float*)d_in[12];
    const float* om_w  = (const float*)d_in[13];
    const float* om_b  = (const float*)d_in[14];
    const float* cl_w  = (const float*)d_in[15];
    const float* cl_b  = (const float*)d_in[16];
    float* out = (float*)d_out;

    float* emb   = symaddr(g_emb);
    float* qkv   = symaddr(g_qkv);
    float* off1  = symaddr(g_off1);
    float* off2  = symaddr(g_off2);
    float* omb   = symaddr(g_om);
    float* wall  = symaddr(g_wall);
    float* vall  = symaddr(g_vall);
    float* fbuf  = symaddr(g_f);
    float* cfwt  = symaddr(g_cfwt);
    float* qkvwt = symaddr(g_qkvwt);
    float* qkvb  = symaddr(g_qkvb);
    float* oc1wt = symaddr(g_oc1wt);
    float* oc2wt = symaddr(g_oc2wt);
    float* omwt  = symaddr(g_omwt);
    float* clwt  = symaddr(g_clwt);

    prep_wt <<<(96*576 +255)/256, 256>>>(cf_w,  cfwt,  96, 576);
    prep_qkv<<<(96*96  +255)/256, 256>>>(wq, wk, wv, bq, bk, bv, qkvwt, qkvb);
    prep_wt <<<(96*1728+255)/256, 256>>>(oc1_w, oc1wt, 96, 1728);
    prep_wt <<<(96*864 +255)/256, 256>>>(oc2_w, oc2wt, 96, 864);
    prep_wt <<<(216*864+255)/256, 256>>>(om_w,  omwt, 216, 864);
    prep_wt <<<(64*864 +255)/256, 256>>>(cl_w,  clwt,  64, 864);

    // emb = conv3x3(fea) — NCHW input, channel-last output
    conv_k<64,96,48,3,true,false,false,false><<<dim3(2,64,12), dim3(16,12)>>>(
        fea, 64*HW, fea, 0, 64, 1, cfwt, cf_b, emb, HW*96, 96, 0, nullptr);

    // qkv = 1x1(emb)
    conv_k<96,288,48,1,false,false,false,false><<<dim3(6,64,12), dim3(16,12)>>>(
        emb, HW*96, emb, 0, 96, 96, qkvwt, qkvb, qkv, HW*288, 288, 0, nullptr);

    // oc1 over ALL 6 pairs in one launch (z = pair*4 + b)
    conv_k<192,96,48,3,false,true,false,true><<<dim3(2,64,24), dim3(16,12)>>>(
        qkv, 0, qkv, 0, 96, 288, oc1wt, oc1_b, off1, HW*96, 96, 0, nullptr);

    // oc2 over all pairs
    conv_k<96,96,48,3,false,true,false,false><<<dim3(2,64,24), dim3(16,12)>>>(
        off1, HW*96, off1, 0, 96, 96, oc2wt, oc2_b, off2, HW*96, 96, 0, nullptr);

    // om over all pairs
    conv_k<96,216,72,3,false,false,false,false><<<dim3(3,64,24), dim3(16,18)>>>(
        off2, HW*96, off2, 0, 96, 96, omwt, om_b, omb, HW*216, 216, 0, nullptr);

    // deformable top-2 attention over all pairs
    attn_k<<<dim3(1024,4,6), 128>>>(qkv, omb, wall, vall);

    // temporal softmax fusion
    fuse_k<<<(12*HW*96+255)/256, 256>>>(wall, vall, fbuf);

    // cl conv -> NCHW output + residual
    conv_k<96,64,64,3,false,false,true,false><<<dim3(1,64,12), dim3(16,16)>>>(
        fbuf, HW*96, fbuf, 0, 96, 96, clwt, cl_b, out, 0, 0, 0, fea);

    (void)in_sizes; (void)n_in; (void)out_size;
}

// round 3
// speedup vs baseline: 1.6854x; 1.2965x over previous
#include <cuda_runtime.h>
#include <math.h>

#define HW 4096
#define WW 64
#define HH 64

typedef unsigned long long u64;

// ---------------- packed f32x2 helpers (FFMA2 — 2x fp32 FMA throughput) ----------------
__device__ __forceinline__ u64 pk(float v) {
    u64 r; asm("mov.b64 %0, {%1, %1};" : "=l"(r) : "f"(v)); return r;
}
__device__ __forceinline__ u64 pk2(float a, float b) {
    u64 r; asm("mov.b64 %0, {%1, %2};" : "=l"(r) : "f"(a), "f"(b)); return r;
}
__device__ __forceinline__ void fma2(u64& d, u64 a, u64 b) {
    asm("fma.rn.f32x2 %0, %1, %2, %0;" : "+l"(d) : "l"(a), "l"(b));
}
__device__ __forceinline__ float2 up2(u64 v) {
    float2 f; asm("mov.b64 {%0, %1}, %2;" : "=f"(f.x), "=f"(f.y) : "l"(v)); return f;
}

// ---------------- device scratch ----------------
__device__ float g_emb [12*HW*96];
__device__ float g_qkv [12*HW*288];
__device__ float g_aqak[24*HW*96];      // aq (12 imgs) | ak (12 imgs)
__device__ float g_off2[6*4*HW*96];
__device__ float g_om  [6*4*HW*216];
__device__ float g_wall[6*4*HW];
__device__ float g_vall[6*4*HW*96];
__device__ float g_f   [12*HW*96];
__device__ float g_cfwt [64*9*96];
__device__ float g_qkvwt[96*288];
__device__ float g_qkvb [288];
__device__ float g_oc1wtq[96*9*96];
__device__ float g_oc1wtk[96*9*96];
__device__ float g_oc2wt[96*9*96];
__device__ float g_omwt [96*9*216];
__device__ float g_clwt [96*9*64];
__device__ float g_zero [256];          // zero-initialized

// ---------------- single prep kernel (all weight transposes) ----------------
__global__ void prep_all(const float* __restrict__ cf_w,
                         const float* __restrict__ wq, const float* __restrict__ wk,
                         const float* __restrict__ wv,
                         const float* __restrict__ bq, const float* __restrict__ bk,
                         const float* __restrict__ bv,
                         const float* __restrict__ oc1_w, const float* __restrict__ oc2_w,
                         const float* __restrict__ om_w,  const float* __restrict__ cl_w)
{
    int i = blockIdx.x*256 + threadIdx.x;
    // cf: 96 x 576
    if (i < 55296) { int d = i/576, k = i%576; g_cfwt[k*96+d] = cf_w[i]; return; }
    i -= 55296;
    // qkv weights: 96 x 96
    if (i < 9216) {
        int d = i/96, c = i%96;
        g_qkvwt[c*288 + d]       = wq[i];
        g_qkvwt[c*288 + 96 + d]  = wk[i];
        g_qkvwt[c*288 + 192 + d] = wv[i];
        return;
    }
    i -= 9216;
    if (i < 96) { g_qkvb[i] = bq[i]; g_qkvb[96+i] = bk[i]; g_qkvb[192+i] = bv[i]; return; }
    i -= 96;
    // oc1: 96 x 1728, split q/k halves
    if (i < 165888) {
        int d = i/1728, rem = i%1728, c = rem/9, tap = rem%9;
        if (c < 96) g_oc1wtq[(c*9+tap)*96 + d] = oc1_w[i];
        else        g_oc1wtk[((c-96)*9+tap)*96 + d] = oc1_w[i];
        return;
    }
    i -= 165888;
    // oc2: 96 x 864
    if (i < 82944) { int d = i/864, k = i%864; g_oc2wt[k*96+d] = oc2_w[i]; return; }
    i -= 82944;
    // om: 216 x 864
    if (i < 186624) { int d = i/864, k = i%864; g_omwt[k*216+d] = om_w[i]; return; }
    i -= 186624;
    // cl: 64 x 864
    if (i < 55296) { int d = i/864, k = i%864; g_clwt[k*64+d] = cl_w[i]; return; }
}

// ---------------- conv: 2 output rows per block, FFMA2 inner ----------------
// MODE: 0 = channel-last input, 1 = NCHW input, 3 = pairsum (lrelu(aq[jj]+ak[ii]+bias2))
template<int CIN, int COUT, int TILE_D, int KS, int MODE, bool LRELU, bool NCHW_OUT>
__global__ void __launch_bounds__(16*(TILE_D/4))
conv_k(const float* __restrict__ inA, int aStride,
       const float* __restrict__ inB, int inPixStride,
       const float* __restrict__ wt, const float* __restrict__ bias,
       const float* __restrict__ bias2,
       float* __restrict__ out, int outImgStride, int outPixStride,
       const float* __restrict__ resid)
{
    constexpr int NT   = 16*(TILE_D/4);
    constexpr int KSQ  = KS*KS;
    constexpr int ROWS = (KS==3) ? 4 : 2;
    constexpr int IPAD = (KS==3) ? 68 : 64;
    constexpr int ICOL = (KS==3) ? 66 : 64;
    constexpr int CCH  = 8;
    constexpr int WIN  = (KS==3) ? 6 : 4;
    __shared__ __align__(16) float s_in[CCH][ROWS][IPAD];
    __shared__ __align__(16) float s_w [CCH][KSQ][TILE_D];

    const int tx  = threadIdx.x, ty = threadIdx.y;
    const int tid = ty*16 + tx;
    const int y0  = 2*blockIdx.y;
    const int z   = blockIdx.z;
    const int d0  = blockIdx.x*TILE_D + 4*ty;
    const int px0 = 4*tx;

    const float* pA;
    const float* pB = nullptr;
    if (MODE == 3) {
        int pair = z >> 2, bb = z & 3;
        int jj = pair >> 1;
        int l  = pair & 1;
        int ii = l ? ((jj==2) ? 1 : 2) : ((jj==0) ? 1 : 0);
        pA = inA + (bb*3 + jj)*HW*96;
        pB = inB + (bb*3 + ii)*HW*96;
    } else {
        pA = inA + (long)z*aStride;
    }

    u64 acc2[2][2][4];  // [row][djpair][px]
#pragma unroll
    for (int h=0; h<2; h++) {
        u64 bv = pk2(bias[d0+2*h], bias[d0+2*h+1]);
#pragma unroll
        for (int o=0; o<2; o++)
#pragma unroll
            for (int pj=0; pj<4; pj++) acc2[o][h][pj] = bv;
    }

    for (int c0 = 0; c0 < CIN; c0 += CCH) {
        __syncthreads();
        // --- input tile (rows y0-1..y0+2 for KS3; y0..y0+1 for KS1) ---
        for (int i = tid; i < CCH*ROWS*ICOL; i += NT) {
            int cc, col, r;
            if (MODE == 1) { col = i % ICOL; cc = (i/ICOL)%CCH; r = i/(ICOL*CCH); }
            else           { cc = i % CCH; col = (i/CCH)%ICOL; r = i/(CCH*ICOL); }
            float v = 0.f;
            int c = c0 + cc;
            if (KS == 3) {
                int xx = col-1, yy = y0-1+r;
                if (xx >= 0 && xx < WW && yy >= 0 && yy < HH) {
                    if (MODE == 1) v = pA[c*HW + yy*WW + xx];
                    else if (MODE == 3) {
                        int pix = yy*WW+xx;
                        float s = pA[pix*96+c] + pB[pix*96+c] + bias2[c];
                        v = (s >= 0.f) ? s : 0.1f*s;
                    } else v = pA[(yy*WW+xx)*inPixStride + c];
                }
            } else {
                int yy = y0+r;
                v = pA[(yy*WW+col)*inPixStride + c];
            }
            s_in[cc][r][col] = v;
        }
        // --- weights ---
        for (int i = tid; i < CCH*KSQ*TILE_D; i += NT) {
            int d = i % TILE_D; int tap = (i/TILE_D)%KSQ; int cc = i/(TILE_D*KSQ);
            s_w[cc][tap][d] = wt[((c0+cc)*KSQ + tap)*COUT + blockIdx.x*TILE_D + d];
        }
        __syncthreads();
#pragma unroll
        for (int cc=0; cc<CCH; cc++) {
            u64 wv[ROWS][WIN];
#pragma unroll
            for (int r=0; r<ROWS; r++) {
                float4 a = *(const float4*)&s_in[cc][r][px0];
                wv[r][0]=pk(a.x); wv[r][1]=pk(a.y); wv[r][2]=pk(a.z); wv[r][3]=pk(a.w);
                if (KS == 3) {
                    wv[r][4]=pk(s_in[cc][r][px0+4]);
                    wv[r][5]=pk(s_in[cc][r][px0+5]);
                }
            }
            if (KS == 3) {
#pragma unroll
                for (int tap=0; tap<9; tap++) {
                    const u64* wp = (const u64*)&s_w[cc][tap][4*ty];
                    u64 w01 = wp[0], w23 = wp[1];
                    const int dy = tap/3, dx = tap%3;
#pragma unroll
                    for (int o=0; o<2; o++)
#pragma unroll
                        for (int pj=0; pj<4; pj++) {
                            u64 a = wv[o+dy][dx+pj];
                            fma2(acc2[o][0][pj], a, w01);
                            fma2(acc2[o][1][pj], a, w23);
                        }
                }
            } else {
                const u64* wp = (const u64*)&s_w[cc][0][4*ty];
                u64 w01 = wp[0], w23 = wp[1];
#pragma unroll
                for (int o=0; o<2; o++)
#pragma unroll
                    for (int pj=0; pj<4; pj++) {
                        u64 a = wv[o][pj];
                        fma2(acc2[o][0][pj], a, w01);
                        fma2(acc2[o][1][pj], a, w23);
                    }
            }
        }
    }

#pragma unroll
    for (int o=0; o<2; o++) {
        float acc[4][4];
#pragma unroll
        for (int h=0; h<2; h++)
#pragma unroll
            for (int pj=0; pj<4; pj++) {
                float2 f = up2(acc2[o][h][pj]);
                acc[2*h][pj] = f.x; acc[2*h+1][pj] = f.y;
            }
        if (LRELU) {
#pragma unroll
            for (int dj=0; dj<4; dj++)
#pragma unroll
                for (int pj=0; pj<4; pj++) {
                    float v = acc[dj][pj];
                    acc[dj][pj] = (v >= 0.f) ? v : 0.1f*v;
                }
        }
        int y = y0 + o;
        if (!NCHW_OUT) {
#pragma unroll
            for (int pj=0; pj<4; pj++) {
                float4 ov = make_float4(acc[0][pj], acc[1][pj], acc[2][pj], acc[3][pj]);
                *(float4*)&out[(long)z*outImgStride + (y*WW + px0 + pj)*outPixStride + d0] = ov;
            }
        } else {
#pragma unroll
            for (int dj=0; dj<4; dj++) {
                int idx = (z*COUT + d0+dj)*HW + y*WW + px0;
                float4 rr = *(const float4*)&resid[idx];
                float4 ov = make_float4(acc[dj][0]+rr.x, acc[dj][1]+rr.y,
                                        acc[dj][2]+rr.z, acc[dj][3]+rr.w);
                *(float4*)&out[idx] = ov;
            }
        }
    }
}

// ---------------- deformable top-2 attention: 1 warp/pixel, float4 gathers ----------------
__global__ void __launch_bounds__(128) attn_k(
    const float* __restrict__ qkv,
    const float* __restrict__ om_all,
    float* __restrict__ w_all, float* __restrict__ v_all)
{
    __shared__ __align__(16) float4 s_wgt[4][72];
    __shared__ __align__(16) int4   s_off[4][72];
    const int warp = threadIdx.x >> 5;
    const int lane = threadIdx.x & 31;
    const int p = blockIdx.x*4 + warp;
    const int b = blockIdx.y;
    const int pair = blockIdx.z;
    const int jj = pair >> 1;
    const int l  = pair & 1;
    const int ii = l ? ((jj==2) ? 1 : 2) : ((jj==0) ? 1 : 0);
    const int y = p >> 6, x = p & 63;
    const float* ombase = om_all + ((pair*4 + b)*HW + (long)p)*216;

    for (int t = lane; t < 72; t += 32) {
        float oy = ombase[t];
        float ox = ombase[72 + t];
        float mm = ombase[144 + t];
        int n = t % 9;
        float m  = 1.f/(1.f + expf(-mm));
        float py = oy + (float)(n/3 - 1 + y);
        float px = ox + (float)(n%3 - 1 + x);
        float y0f = floorf(py), x0f = floorf(px);
        float wy = py - y0f, wx = px - x0f;
        int iy0 = (int)y0f, ix0 = (int)x0f;
        int iy1 = iy0 + 1, ix1 = ix0 + 1;
        float vy0 = (iy0 >= 0 && iy0 < HH) ? 1.f : 0.f;
        float vy1 = (iy1 >= 0 && iy1 < HH) ? 1.f : 0.f;
        float vx0 = (ix0 >= 0 && ix0 < WW) ? 1.f : 0.f;
        float vx1 = (ix1 >= 0 && ix1 < WW) ? 1.f : 0.f;
        int cy0 = min(max(iy0,0),HH-1), cy1 = min(max(iy1,0),HH-1);
        int cx0 = min(max(ix0,0),WW-1), cx1 = min(max(ix1,0),WW-1);
        float wy0 = 1.f - wy, wx0 = 1.f - wx;
        s_wgt[warp][t] = make_float4(m*wy0*wx0*vy0*vx0, m*wy0*wx *vy0*vx1,
                                     m*wy *wx0*vy1*vx0, m*wy *wx *vy1*vx1);
        s_off[warp][t] = make_int4((cy0*WW+cx0)*288, (cy0*WW+cx1)*288,
                                   (cy1*WW+cx0)*288, (cy1*WW+cx1)*288);
    }
    __syncwarp();

    const bool act = (lane < 24);
    const int g = lane / 3;                 // group of channels 4*lane..4*lane+3
    const float* qp = qkv + (((b*3+jj)*HW + (long)p)*288);
    float4 qv = make_float4(0,0,0,0);
    if (act) qv = __ldg((const float4*)(qp + 4*lane));
    const float* kb = qkv + (b*3+ii)*(long)HW*288 + 96 + 4*lane;

    float rel[9];
#pragma unroll
    for (int n=0; n<9; n++) {
        float part = 0.f;
        if (act) {
            float4 W = s_wgt[warp][g*9+n];
            int4   O = s_off[warp][g*9+n];
            float4 k0 = __ldg((const float4*)(kb + O.x));
            float4 k1 = __ldg((const float4*)(kb + O.y));
            float4 k2 = __ldg((const float4*)(kb + O.z));
            float4 k3 = __ldg((const float4*)(kb + O.w));
            float sx = W.x*k0.x + W.y*k1.x + W.z*k2.x + W.w*k3.x;
            float sy = W.x*k0.y + W.y*k1.y + W.z*k2.y + W.w*k3.y;
            float sz = W.x*k0.z + W.y*k1.z + W.z*k2.z + W.w*k3.z;
            float sw = W.x*k0.w + W.y*k1.w + W.z*k2.w + W.w*k3.w;
            part = sx*qv.x + sy*qv.y + sz*qv.z + sw*qv.w;
        }
#pragma unroll
        for (int o=16; o>0; o>>=1) part += __shfl_xor_sync(0xffffffffu, part, o);
        rel[n] = part;
    }

    float b1 = rel[0]; int i1 = 0; float b2 = -1e30f; int i2 = 0;
#pragma unroll
    for (int n=1; n<9; n++) {
        if (rel[n] > b1)      { b2 = b1; i2 = i1; b1 = rel[n]; i1 = n; }
        else if (rel[n] > b2) { b2 = rel[n]; i2 = n; }
    }
    float c1 = 1.f/(1.f + expf(b2 - b1));
    float c2 = 1.f - c1;
    if (lane == 0) w_all[(pair*4 + b)*HW + p] = c1*b1 + c2*b2;

    if (act) {
        const float* vb = kb + 96;
        float4 W1 = s_wgt[warp][g*9+i1]; int4 O1 = s_off[warp][g*9+i1];
        float4 W2 = s_wgt[warp][g*9+i2]; int4 O2 = s_off[warp][g*9+i2];
        float4 a0 = __ldg((const float4*)(vb + O1.x));
        float4 a1 = __ldg((const float4*)(vb + O1.y));
        float4 a2 = __ldg((const float4*)(vb + O1.z));
        float4 a3 = __ldg((const float4*)(vb + O1.w));
        float4 b0 = __ldg((const float4*)(vb + O2.x));
        float4 bb1= __ldg((const float4*)(vb + O2.y));
        float4 b2v= __ldg((const float4*)(vb + O2.z));
        float4 b3 = __ldg((const float4*)(vb + O2.w));
        float4 ov;
        ov.x = c1*(W1.x*a0.x + W1.y*a1.x + W1.z*a2.x + W1.w*a3.x)
             + c2*(W2.x*b0.x + W2.y*bb1.x + W2.z*b2v.x + W2.w*b3.x);
        ov.y = c1*(W1.x*a0.y + W1.y*a1.y + W1.z*a2.y + W1.w*a3.y)
             + c2*(W2.x*b0.y + W2.y*bb1.y + W2.z*b2v.y + W2.w*b3.y);
        ov.z = c1*(W1.x*a0.z + W1.y*a1.z + W1.z*a2.z + W1.w*a3.z)
             + c2*(W2.x*b0.z + W2.y*bb1.z + W2.z*b2v.z + W2.w*b3.z);
        ov.w = c1*(W1.x*a0.w + W1.y*a1.w + W1.z*a2.w + W1.w*a3.w)
             + c2*(W2.x*b0.w + W2.y*bb1.w + W2.z*b2v.w + W2.w*b3.w);
        *(float4*)(v_all + ((pair*4 + b)*HW + (long)p)*96 + 4*lane) = ov;
    }
}

// ---------------- fuse: softmax over the 2 pairs per target frame ----------------
__global__ void fuse_k(const float* __restrict__ w_all, const float* __restrict__ v_all,
                       float* __restrict__ f)
{
    int i = blockIdx.x*256 + threadIdx.x;
    if (i >= 12*HW*96) return;
    int c = i % 96; int rest = i / 96; int p = rest % HW; int img = rest / HW;
    int jj = img % 3, b = img / 3;
    int p0 = jj*2, p1 = jj*2+1;
    float w0 = w_all[(p0*4 + b)*HW + p];
    float w1 = w_all[(p1*4 + b)*HW + p];
    float mx = fmaxf(w0, w1);
    float e0 = expf(w0-mx), e1 = expf(w1-mx);
    float inv = 1.f/(e0+e1);
    float v0 = v_all[((p0*4+b)*HW + (long)p)*96 + c];
    float v1 = v_all[((p1*4+b)*HW + (long)p)*96 + c];
    f[i] = (e0*v0 + e1*v1)*inv;
}

// ---------------- host ----------------
static float* symaddr(const void* s) {
    void* p = nullptr;
    cudaGetSymbolAddress(&p, s);
    return (float*)p;
}

extern "C" void kernel_launch(void* const* d_in, const int* in_sizes, int n_in,
                              void* d_out, int out_size)
{
    const float* fea   = (const float*)d_in[0];
    const float* cf_w  = (const float*)d_in[1];
    const float* cf_b  = (const float*)d_in[2];
    const float* wq    = (const float*)d_in[3];
    const float* bq    = (const float*)d_in[4];
    const float* wk    = (const float*)d_in[5];
    const float* bk    = (const float*)d_in[6];
    const float* wv    = (const float*)d_in[7];
    const float* bv    = (const float*)d_in[8];
    const float* oc1_w = (const float*)d_in[9];
    const float* oc1_b = (const float*)d_in[10];
    const float* oc2_w = (const float*)d_in[11];
    const float* oc2_b = (const float*)d_in[12];
    const float* om_w  = (const float*)d_in[13];
    const float* om_b  = (const float*)d_in[14];
    const float* cl_w  = (const float*)d_in[15];
    const float* cl_b  = (const float*)d_in[16];
    float* out = (float*)d_out;

    float* emb   = symaddr(g_emb);
    float* qkv   = symaddr(g_qkv);
    float* aq    = symaddr(g_aqak);
    float* ak    = aq + 12*HW*96;
    float* off2  = symaddr(g_off2);
    float* omb   = symaddr(g_om);
    float* wall  = symaddr(g_wall);
    float* vall  = symaddr(g_vall);
    float* fbuf  = symaddr(g_f);
    float* cfwt  = symaddr(g_cfwt);
    float* qkvwt = symaddr(g_qkvwt);
    float* qkvb  = symaddr(g_qkvb);
    float* oc1wtq= symaddr(g_oc1wtq);
    float* oc1wtk= symaddr(g_oc1wtk);
    float* oc2wt = symaddr(g_oc2wt);
    float* omwt  = symaddr(g_omwt);
    float* clwt  = symaddr(g_clwt);
    float* zero  = symaddr(g_zero);

    // 1) all weight prep in ONE launch
    prep_all<<<2171, 256>>>(cf_w, wq, wk, wv, bq, bk, bv, oc1_w, oc2_w, om_w, cl_w);

    // 2) emb = conv3x3(fea) — NCHW in, channel-last out
    conv_k<64,96,48,3,1,false,false><<<dim3(2,32,12), dim3(16,12)>>>(
        fea, 64*HW, nullptr, 1, cfwt, cf_b, nullptr, emb, HW*96, 96, nullptr);

    // 3) qkv = 1x1(emb)
    conv_k<96,288,48,1,0,false,false><<<dim3(6,32,12), dim3(16,12)>>>(
        emb, HW*96, nullptr, 96, qkvwt, qkvb, nullptr, qkv, HW*288, 288, nullptr);

    // 4) oc1 split: aq = conv_q(q_t), ak = conv_k(k_t), per frame (12 imgs each)
    conv_k<96,96,48,3,0,false,false><<<dim3(2,32,12), dim3(16,12)>>>(
        qkv, HW*288, nullptr, 288, oc1wtq, zero, nullptr, aq, HW*96, 96, nullptr);
    conv_k<96,96,48,3,0,false,false><<<dim3(2,32,12), dim3(16,12)>>>(
        qkv+96, HW*288, nullptr, 288, oc1wtk, zero, nullptr, ak, HW*96, 96, nullptr);

    // 5) oc2 over 24 (pair,b) images; input = lrelu(aq[jj]+ak[ii]+oc1_b) fused in fill
    conv_k<96,96,48,3,3,true,false><<<dim3(2,32,24), dim3(16,12)>>>(
        aq, 0, ak, 96, oc2wt, oc2_b, oc1_b, off2, HW*96, 96, nullptr);

    // 6) om over 24 images
    conv_k<96,216,72,3,0,false,false><<<dim3(3,32,24), dim3(16,18)>>>(
        off2, HW*96, nullptr, 96, omwt, om_b, nullptr, omb, HW*216, 216, nullptr);

    // 7) deformable top-2 attention over all pairs
    attn_k<<<dim3(1024,4,6), 128>>>(qkv, omb, wall, vall);

    // 8) temporal softmax fusion
    fuse_k<<<(12*HW*96+255)/256, 256>>>(wall, vall, fbuf);

    // 9) cl conv -> NCHW output + residual
    conv_k<96,64,64,3,0,false,true><<<dim3(1,32,12), dim3(16,16)>>>(
        fbuf, HW*96, nullptr, 96, clwt, cl_b, nullptr, out, 0, 0, fea);

    (void)in_sizes; (void)n_in; (void)out_size;
}